// round 13
// baseline (speedup 1.0000x reference)
#include <cuda_runtime.h>
#include <cuda_bf16.h>
#include <cstdint>

// Problem constants
#define NN   10000
#define EE   30000
#define D_IN 64
#define E_DIM 16
#define H1   128
#define H2   64
#define CC   10
#define KX   17            // E_DIM + 1 bias slot
#define Q1W  (KX*H2)       // 1088
#define Q2W  (KX*CC)       // 170
#define B1W  (Q1W + H2)    // 1152
#define B2W  (Q2W + CC)    // 180

// ---------------- device scratch ----------------
__device__ float g_h1[NN*H1];       // tf32-rounded at write
__device__ float g_q1[NN*Q1W];
__device__ float g_agg1[NN*H2];
__device__ float g_h2[NN*H2];       // tf32-rounded at write
__device__ float g_q2[NN*Q2W];
__device__ float g_agg2[NN*CC];
__device__ float g_M1[H1*B1W];      // tf32-rounded
__device__ float g_M2[H2*B2W];      // tf32-rounded
__device__ float g_xr[NN*D_IN];     // tf32-rounded copy of x
__device__ float g_W1r[D_IN*H1];    // tf32-rounded copy of W1

// ---------------- helpers ----------------
__device__ __forceinline__ uint32_t f2tf32(float f) {
    uint32_t r;
    asm("cvt.rna.tf32.f32 %0, %1;" : "=r"(r) : "f"(f));
    return r;
}
__device__ __forceinline__ float tf32r(float f) { return __uint_as_float(f2tf32(f)); }

__device__ __forceinline__ void mma_tf32(float c[4], uint32_t a0, uint32_t a1,
                                         uint32_t a2, uint32_t a3,
                                         uint32_t b0, uint32_t b1) {
    asm volatile(
        "mma.sync.aligned.m16n8k8.row.col.f32.tf32.tf32.f32 "
        "{%0,%1,%2,%3}, {%4,%5,%6,%7}, {%8,%9}, {%0,%1,%2,%3};"
        : "+f"(c[0]), "+f"(c[1]), "+f"(c[2]), "+f"(c[3])
        : "r"(a0), "r"(a1), "r"(a2), "r"(a3), "r"(b0), "r"(b1));
}

__device__ __forceinline__ void cp16(uint32_t smem_dst, const void* gsrc, int src_bytes) {
    asm volatile("cp.async.ca.shared.global [%0], [%1], 16, %2;"
                 :: "r"(smem_dst), "l"(gsrc), "r"(src_bytes));
}
__device__ __forceinline__ void cp_commit() { asm volatile("cp.async.commit_group;"); }
template <int N> __device__ __forceinline__ void cp_wait() {
    asm volatile("cp.async.wait_group %0;" :: "n"(N));
}

// ---------------- pack / pre-round kernels ----------------
__global__ void pack_m1(const float* __restrict__ We1, const float* __restrict__ be1,
                        const float* __restrict__ root1) {
    int idx = blockIdx.x * blockDim.x + threadIdx.x;
    if (idx >= H1 * B1W) return;
    int i = idx / B1W;
    int col = idx - i * B1W;
    float v;
    if (col < Q1W) {
        int k = col / H2;
        int o = col - k * H2;
        v = (k < E_DIM) ? We1[k * (H1 * H2) + i * H2 + o] : be1[i * H2 + o];
    } else {
        v = root1[i * H2 + (col - Q1W)];
    }
    g_M1[idx] = tf32r(v);
}

__global__ void pack_m2(const float* __restrict__ We2, const float* __restrict__ be2,
                        const float* __restrict__ root2) {
    int idx = blockIdx.x * blockDim.x + threadIdx.x;
    if (idx >= H2 * B2W) return;
    int j = idx / B2W;
    int col = idx - j * B2W;
    float v;
    if (col < Q2W) {
        int k = col / CC;
        int c = col - k * CC;
        v = (k < E_DIM) ? We2[k * (H2 * CC) + j * CC + c] : be2[j * CC + c];
    } else {
        v = root2[j * CC + (col - Q2W)];
    }
    g_M2[idx] = tf32r(v);
}

__global__ void round_x(const float* __restrict__ x, int n) {
    int i = blockIdx.x * blockDim.x + threadIdx.x;
    if (i < n) g_xr[i] = tf32r(x[i]);
}
__global__ void round_w1(const float* __restrict__ W1) {
    int i = blockIdx.x * blockDim.x + threadIdx.x;
    if (i < D_IN * H1) g_W1r[i] = tf32r(W1[i]);
}

// ========== tf32 tensor-core GEMM, cp.async double-buffered, split epilogue ==========
// Operands MUST be pre-rounded to tf32. C cols [0,S) -> Cq (+biasQ,+relu,+round opt);
// cols [S,Nn) -> Ca (+biasA). Requires K % 16 == 0, Nn % 4 == 0.
#define GM 128
#define GN 128
#define GKT 16
#define AKP 20     // As row pad (80B, 16B-aligned rows)
#define BNP 136    // Bs row pad (544B, 16B-aligned rows)
__global__ __launch_bounds__(256) void tgemm(
    const float* __restrict__ A, const float* __restrict__ B,
    float* __restrict__ Cq, float* __restrict__ Ca,
    int M, int Nn, int K, int S,
    const float* __restrict__ biasQ, const float* __restrict__ biasA,
    int do_relu, int do_round)
{
    __shared__ __align__(16) uint32_t As[2][GM][AKP];
    __shared__ __align__(16) uint32_t Bs[2][GKT][BNP];

    int tid  = threadIdx.x;
    int lane = tid & 31;
    int wid  = tid >> 5;
    int bm0 = blockIdx.y * GM;
    int bn0 = blockIdx.x * GN;
    int wm = (wid & 1) * 64;
    int wn = (wid >> 1) * 32;

    // staging coords
    int arow = tid >> 1;          // 0..127
    int ak   = (tid & 1) * 8;     // 0 or 8
    int brow = tid >> 4;          // 0..15
    int bcol = (tid & 15) * 8;    // 0..120
    bool aok = (bm0 + arow) < M;
    const float* Abase = A + (size_t)(bm0 + arow) * K + ak;
    int bok0 = (bn0 + bcol)     < Nn ? 16 : 0;
    int bok1 = (bn0 + bcol + 4) < Nn ? 16 : 0;
    int aokb = aok ? 16 : 0;

    float c[4][4][4];
    #pragma unroll
    for (int mt = 0; mt < 4; mt++)
        #pragma unroll
        for (int nt = 0; nt < 4; nt++)
            #pragma unroll
            for (int r = 0; r < 4; r++) c[mt][nt][r] = 0.f;

    int lq = lane & 3;
    int lg = lane >> 2;
    int ntls = K / GKT;

    // stage tile kt into buffer b
    auto stage = [&](int kt, int b) {
        int k0 = kt * GKT;
        cp16((uint32_t)__cvta_generic_to_shared(&As[b][arow][ak]),     Abase + k0,     aokb);
        cp16((uint32_t)__cvta_generic_to_shared(&As[b][arow][ak + 4]), Abase + k0 + 4, aokb);
        const float* Brow = B + (size_t)(k0 + brow) * Nn + bn0 + bcol;
        cp16((uint32_t)__cvta_generic_to_shared(&Bs[b][brow][bcol]),     Brow,     bok0);
        cp16((uint32_t)__cvta_generic_to_shared(&Bs[b][brow][bcol + 4]), Brow + 4, bok1);
    };

    stage(0, 0);
    cp_commit();

    for (int kt = 0; kt < ntls; kt++) {
        int cur = kt & 1;
        if (kt + 1 < ntls) {
            stage(kt + 1, cur ^ 1);
            cp_commit();
            cp_wait<1>();
        } else {
            cp_wait<0>();
        }
        __syncthreads();

        #pragma unroll
        for (int kk = 0; kk < GKT; kk += 8) {
            uint32_t af[4][4];
            #pragma unroll
            for (int mt = 0; mt < 4; mt++) {
                int m = wm + mt * 16 + lg;
                af[mt][0] = As[cur][m    ][kk + lq];
                af[mt][1] = As[cur][m + 8][kk + lq];
                af[mt][2] = As[cur][m    ][kk + lq + 4];
                af[mt][3] = As[cur][m + 8][kk + lq + 4];
            }
            uint32_t bf[4][2];
            #pragma unroll
            for (int nt = 0; nt < 4; nt++) {
                int n = wn + nt * 8 + lg;
                bf[nt][0] = Bs[cur][kk + lq    ][n];
                bf[nt][1] = Bs[cur][kk + lq + 4][n];
            }
            #pragma unroll
            for (int mt = 0; mt < 4; mt++)
                #pragma unroll
                for (int nt = 0; nt < 4; nt++)
                    mma_tf32(c[mt][nt], af[mt][0], af[mt][1], af[mt][2], af[mt][3],
                             bf[nt][0], bf[nt][1]);
        }
        __syncthreads();
    }

    int Wa = Nn - S;
    #pragma unroll
    for (int mt = 0; mt < 4; mt++) {
        #pragma unroll
        for (int rh = 0; rh < 2; rh++) {
            int gm = bm0 + wm + mt * 16 + rh * 8 + lg;
            if (gm >= M) continue;
            #pragma unroll
            for (int nt = 0; nt < 4; nt++) {
                #pragma unroll
                for (int l = 0; l < 2; l++) {
                    int gn = bn0 + wn + nt * 8 + 2 * lq + l;
                    if (gn >= Nn) continue;
                    float v = c[mt][nt][rh * 2 + l];
                    if (gn < S) {
                        if (biasQ) v += biasQ[gn];
                        if (do_relu) v = fmaxf(v, 0.f);
                        if (do_round) v = tf32r(v);
                        Cq[(size_t)gm * S + gn] = v;
                    } else {
                        if (biasA) v += biasA[gn - S];
                        Ca[(size_t)gm * Wa + (gn - S)] = v;
                    }
                }
            }
        }
    }
}

// ---------------- edge kernels (warp per edge; edge_index is int32) ----------------
__global__ void edge_l1(const float* __restrict__ ea, const int* __restrict__ ei, int E) {
    int e = blockIdx.x * (blockDim.x >> 5) + (threadIdx.x >> 5);
    if (e >= E) return;
    int lane = threadIdx.x & 31;
    float cv = (lane < E_DIM) ? ea[(size_t)e * E_DIM + lane] : (lane == E_DIM ? 1.f : 0.f);
    int src = ei[e];
    int dst = ei[E + e];
    if ((unsigned)src >= NN || (unsigned)dst >= NN) return;
    const float* q = g_q1 + (size_t)src * Q1W;
    float a0 = 0.f, a1 = 0.f;
    #pragma unroll
    for (int k = 0; k < KX; k++) {
        float ck = __shfl_sync(0xffffffffu, cv, k);
        a0 = fmaf(ck, q[k * H2 + lane], a0);
        a1 = fmaf(ck, q[k * H2 + lane + 32], a1);
    }
    atomicAdd(&g_agg1[(size_t)dst * H2 + lane], a0);
    atomicAdd(&g_agg1[(size_t)dst * H2 + lane + 32], a1);
}

__global__ void edge_l2(const float* __restrict__ ea, const int* __restrict__ ei, int E) {
    int e = blockIdx.x * (blockDim.x >> 5) + (threadIdx.x >> 5);
    if (e >= E) return;
    int lane = threadIdx.x & 31;
    float cv = (lane < E_DIM) ? ea[(size_t)e * E_DIM + lane] : (lane == E_DIM ? 1.f : 0.f);
    int src = ei[e];
    int dst = ei[E + e];
    if ((unsigned)src >= NN || (unsigned)dst >= NN) return;
    const float* q = g_q2 + (size_t)src * Q2W;
    float a = 0.f;
    #pragma unroll
    for (int k = 0; k < KX; k++) {
        float ck = __shfl_sync(0xffffffffu, cv, k);
        if (lane < CC) a = fmaf(ck, q[k * CC + lane], a);
    }
    if (lane < CC) atomicAdd(&g_agg2[(size_t)dst * CC + lane], a);
}

// ---------------- relu + log_softmax ----------------
__global__ void relu_copy(int n) {
    int i = blockIdx.x * blockDim.x + threadIdx.x;
    if (i < n) g_h2[i] = tf32r(fmaxf(g_agg1[i], 0.f));
}

__global__ void log_softmax_rows(float* __restrict__ out, int n) {
    int r = blockIdx.x * blockDim.x + threadIdx.x;
    if (r >= n) return;
    const float* z = g_agg2 + (size_t)r * CC;
    float m = z[0];
    #pragma unroll
    for (int c = 1; c < CC; c++) m = fmaxf(m, z[c]);
    float s = 0.f;
    #pragma unroll
    for (int c = 0; c < CC; c++) s += __expf(z[c] - m);
    float ls = m + logf(s);
    #pragma unroll
    for (int c = 0; c < CC; c++) out[(size_t)r * CC + c] = z[c] - ls;
}

// ---------------- launch ----------------
extern "C" void kernel_launch(void* const* d_in, const int* in_sizes, int n_in,
                              void* d_out, int out_size)
{
    const float* x     = (const float*)d_in[0];
    const float* ea    = (const float*)d_in[1];
    const int*   ei    = (const int*)d_in[2];
    const float* W1    = (const float*)d_in[3];
    const float* b1    = (const float*)d_in[4];
    const float* We1   = (const float*)d_in[5];
    const float* be1   = (const float*)d_in[6];
    const float* root1 = (const float*)d_in[7];
    const float* bias1 = (const float*)d_in[8];
    const float* We2   = (const float*)d_in[9];
    const float* be2   = (const float*)d_in[10];
    const float* root2 = (const float*)d_in[11];
    const float* bias2 = (const float*)d_in[12];
    float* out = (float*)d_out;

    int N = in_sizes[0] / D_IN;
    int E = in_sizes[2] / 2;

    float *p_h1, *p_q1, *p_agg1, *p_h2, *p_q2, *p_M1, *p_M2, *p_agg2, *p_xr, *p_W1r;
    cudaGetSymbolAddress((void**)&p_h1,   g_h1);
    cudaGetSymbolAddress((void**)&p_q1,   g_q1);
    cudaGetSymbolAddress((void**)&p_agg1, g_agg1);
    cudaGetSymbolAddress((void**)&p_h2,   g_h2);
    cudaGetSymbolAddress((void**)&p_q2,   g_q2);
    cudaGetSymbolAddress((void**)&p_M1,   g_M1);
    cudaGetSymbolAddress((void**)&p_M2,   g_M2);
    cudaGetSymbolAddress((void**)&p_agg2, g_agg2);
    cudaGetSymbolAddress((void**)&p_xr,   g_xr);
    cudaGetSymbolAddress((void**)&p_W1r,  g_W1r);

    dim3 blk(256);

    pack_m1<<<(H1 * B1W + 255) / 256, blk>>>(We1, be1, root1);
    pack_m2<<<(H2 * B2W + 255) / 256, blk>>>(We2, be2, root2);
    round_x<<<(N * D_IN + 255) / 256, blk>>>(x, N * D_IN);
    round_w1<<<(D_IN * H1 + 255) / 256, blk>>>(W1);

    // h1 = round(relu(x @ W1 + b1))     [N,64]@[64,128]
    {
        dim3 g((H1 + GN - 1) / GN, (N + GM - 1) / GM);
        tgemm<<<g, blk>>>(p_xr, p_W1r, p_h1, p_h1, N, H1, D_IN, H1, b1, nullptr, 1, 1);
    }
    // fused q1|agg1 = h1 @ [M1|root1]   [N,128]@[128,1152]; split at 1088
    {
        dim3 g((B1W + GN - 1) / GN, (N + GM - 1) / GM);
        tgemm<<<g, blk>>>(p_h1, p_M1, p_q1, p_agg1, N, B1W, H1, Q1W, nullptr, bias1, 0, 0);
    }
    edge_l1<<<(E + 3) / 4, 128>>>(ea, ei, E);
    relu_copy<<<(N * H2 + 255) / 256, blk>>>(N * H2);
    // fused q2|agg2 = h2 @ [M2|root2]   [N,64]@[64,180]; split at 170
    {
        dim3 g((B2W + GN - 1) / GN, (N + GM - 1) / GM);
        tgemm<<<g, blk>>>(p_h2, p_M2, p_q2, p_agg2, N, B2W, H2, Q2W, nullptr, bias2, 0, 0);
    }
    edge_l2<<<(E + 3) / 4, 128>>>(ea, ei, E);
    log_softmax_rows<<<(N + 255) / 256, blk>>>(out, N);
}

// round 15
// speedup vs baseline: 1.1115x; 1.1115x over previous
#include <cuda_runtime.h>
#include <cuda_bf16.h>
#include <cstdint>

// Problem constants
#define NN   10000
#define EE   30000
#define D_IN 64
#define E_DIM 16
#define H1   128
#define H2   64
#define CC   10
#define KX   17            // E_DIM + 1 bias slot
#define Q1W  (KX*H2)       // 1088
#define Q2W  (KX*CC)       // 170
#define B1W  (Q1W + H2)    // 1152
#define B2W  (Q2W + CC)    // 180

// ---------------- device scratch ----------------
__device__ float g_h1[NN*H1];       // tf32-rounded at write
__device__ float g_q1[NN*Q1W];
__device__ float g_agg1[NN*H2];
__device__ float g_h2[NN*H2];       // tf32-rounded at write
__device__ float g_q2[NN*Q2W];
__device__ float g_agg2[NN*CC];
__device__ float g_M1[H1*B1W];      // tf32-rounded
__device__ float g_M2[H2*B2W];      // tf32-rounded
__device__ float g_xr[NN*D_IN];     // tf32-rounded copy of x
__device__ float g_W1r[D_IN*H1];    // tf32-rounded copy of W1

// ---------------- helpers ----------------
__device__ __forceinline__ uint32_t f2tf32(float f) {
    uint32_t r;
    asm("cvt.rna.tf32.f32 %0, %1;" : "=r"(r) : "f"(f));
    return r;
}
__device__ __forceinline__ float tf32r(float f) { return __uint_as_float(f2tf32(f)); }

__device__ __forceinline__ void mma_tf32(float c[4], uint32_t a0, uint32_t a1,
                                         uint32_t a2, uint32_t a3,
                                         uint32_t b0, uint32_t b1) {
    asm volatile(
        "mma.sync.aligned.m16n8k8.row.col.f32.tf32.tf32.f32 "
        "{%0,%1,%2,%3}, {%4,%5,%6,%7}, {%8,%9}, {%0,%1,%2,%3};"
        : "+f"(c[0]), "+f"(c[1]), "+f"(c[2]), "+f"(c[3])
        : "r"(a0), "r"(a1), "r"(a2), "r"(a3), "r"(b0), "r"(b1));
}

__device__ __forceinline__ void cp16(uint32_t smem_dst, const void* gsrc, int src_bytes) {
    asm volatile("cp.async.ca.shared.global [%0], [%1], 16, %2;"
                 :: "r"(smem_dst), "l"(gsrc), "r"(src_bytes));
}
__device__ __forceinline__ void cp_commit() { asm volatile("cp.async.commit_group;"); }
template <int N> __device__ __forceinline__ void cp_wait() {
    asm volatile("cp.async.wait_group %0;" :: "n"(N));
}

// ---------------- merged prep kernel: pack M1, pack M2, round x, round W1 ----------------
#define T_M1  (H1*B1W)                       // 147456
#define T_M2  (T_M1 + H2*B2W)                // +11520
#define T_X   (T_M2 + NN*D_IN)               // +640000
#define T_W1  (T_X + D_IN*H1)                // +8192
__global__ void prep(const float* __restrict__ We1, const float* __restrict__ be1,
                     const float* __restrict__ root1,
                     const float* __restrict__ We2, const float* __restrict__ be2,
                     const float* __restrict__ root2,
                     const float* __restrict__ x, const float* __restrict__ W1) {
    int idx = blockIdx.x * blockDim.x + threadIdx.x;
    if (idx < T_M1) {
        int i = idx / B1W;
        int col = idx - i * B1W;
        float v;
        if (col < Q1W) {
            int k = col / H2;
            int o = col - k * H2;
            v = (k < E_DIM) ? We1[k * (H1 * H2) + i * H2 + o] : be1[i * H2 + o];
        } else {
            v = root1[i * H2 + (col - Q1W)];
        }
        g_M1[idx] = tf32r(v);
    } else if (idx < T_M2) {
        int t = idx - T_M1;
        int j = t / B2W;
        int col = t - j * B2W;
        float v;
        if (col < Q2W) {
            int k = col / CC;
            int c = col - k * CC;
            v = (k < E_DIM) ? We2[k * (H2 * CC) + j * CC + c] : be2[j * CC + c];
        } else {
            v = root2[j * CC + (col - Q2W)];
        }
        g_M2[t] = tf32r(v);
    } else if (idx < T_X) {
        int t = idx - T_M2;
        g_xr[t] = tf32r(x[t]);
    } else if (idx < T_W1) {
        int t = idx - T_X;
        g_W1r[t] = tf32r(W1[t]);
    }
}

// ========== tf32 tensor-core GEMM, GKT=32, cp.async double-buffered, split epilogue ==========
// Operands MUST be pre-rounded to tf32. C cols [0,S) -> Cq (+biasQ,+relu,+round opt);
// cols [S,Nn) -> Ca (+biasA). Requires K % 32 == 0, Nn % 4 == 0. Dynamic smem.
#define GM 128
#define GN 128
#define GKT 32
#define AKP 36     // As row pad: 144B rows, 16B aligned, conflict-free
#define BNP 136    // Bs row pad: 544B rows
#define ASZ (GM*AKP)          // 4608 u32 per buffer
#define BSZ (GKT*BNP)         // 4352 u32 per buffer
#define SMEM_BYTES ((2*ASZ + 2*BSZ) * 4)   // 71680
__global__ __launch_bounds__(256) void tgemm(
    const float* __restrict__ A, const float* __restrict__ B,
    float* __restrict__ Cq, float* __restrict__ Ca,
    int M, int Nn, int K, int S,
    const float* __restrict__ biasQ, const float* __restrict__ biasA,
    int do_relu, int do_round)
{
    extern __shared__ __align__(16) uint32_t sm[];
    uint32_t* Asb = sm;                 // 2 x [GM][AKP]
    uint32_t* Bsb = sm + 2 * ASZ;       // 2 x [GKT][BNP]

    int tid  = threadIdx.x;
    int lane = tid & 31;
    int wid  = tid >> 5;
    int bm0 = blockIdx.y * GM;
    int bn0 = blockIdx.x * GN;
    int wm = (wid & 1) * 64;
    int wn = (wid >> 1) * 32;

    // staging coords: A 128x32 (16 floats/thread), B 32x128 (16 floats/thread)
    int arow = tid >> 1;            // 0..127
    int ak   = (tid & 1) * 16;      // 0 or 16
    int brow = tid >> 3;            // 0..31
    int bcol = (tid & 7) * 16;      // 0..112
    bool aok = (bm0 + arow) < M;
    int aokb = aok ? 16 : 0;
    const float* Abase = A + (size_t)(bm0 + arow) * K + ak;
    int bokb[4];
    #pragma unroll
    for (int c = 0; c < 4; c++) bokb[c] = (bn0 + bcol + c * 4) < Nn ? 16 : 0;

    float acc[4][4][4];
    #pragma unroll
    for (int mt = 0; mt < 4; mt++)
        #pragma unroll
        for (int nt = 0; nt < 4; nt++)
            #pragma unroll
            for (int r = 0; r < 4; r++) acc[mt][nt][r] = 0.f;

    int lq = lane & 3;
    int lg = lane >> 2;
    int ntls = K / GKT;

    auto stage = [&](int kt, int b) {
        int k0 = kt * GKT;
        uint32_t adst = (uint32_t)__cvta_generic_to_shared(Asb + b * ASZ + arow * AKP + ak);
        #pragma unroll
        for (int c = 0; c < 4; c++)
            cp16(adst + c * 16, Abase + k0 + c * 4, aokb);
        const float* Brow = B + (size_t)(k0 + brow) * Nn + bn0 + bcol;
        uint32_t bdst = (uint32_t)__cvta_generic_to_shared(Bsb + b * BSZ + brow * BNP + bcol);
        #pragma unroll
        for (int c = 0; c < 4; c++)
            cp16(bdst + c * 16, Brow + c * 4, bokb[c]);
    };

    stage(0, 0);
    cp_commit();

    for (int kt = 0; kt < ntls; kt++) {
        int cur = kt & 1;
        if (kt + 1 < ntls) {
            stage(kt + 1, cur ^ 1);
            cp_commit();
            cp_wait<1>();
        } else {
            cp_wait<0>();
        }
        __syncthreads();

        const uint32_t* As = Asb + cur * ASZ;
        const uint32_t* Bs = Bsb + cur * BSZ;
        #pragma unroll
        for (int kk = 0; kk < GKT; kk += 8) {
            uint32_t af[4][4];
            #pragma unroll
            for (int mt = 0; mt < 4; mt++) {
                int m = wm + mt * 16 + lg;
                af[mt][0] = As[(m    ) * AKP + kk + lq];
                af[mt][1] = As[(m + 8) * AKP + kk + lq];
                af[mt][2] = As[(m    ) * AKP + kk + lq + 4];
                af[mt][3] = As[(m + 8) * AKP + kk + lq + 4];
            }
            uint32_t bf[4][2];
            #pragma unroll
            for (int nt = 0; nt < 4; nt++) {
                int n = wn + nt * 8 + lg;
                bf[nt][0] = Bs[(kk + lq    ) * BNP + n];
                bf[nt][1] = Bs[(kk + lq + 4) * BNP + n];
            }
            #pragma unroll
            for (int mt = 0; mt < 4; mt++)
                #pragma unroll
                for (int nt = 0; nt < 4; nt++)
                    mma_tf32(acc[mt][nt], af[mt][0], af[mt][1], af[mt][2], af[mt][3],
                             bf[nt][0], bf[nt][1]);
        }
        __syncthreads();
    }

    int Wa = Nn - S;
    #pragma unroll
    for (int mt = 0; mt < 4; mt++) {
        #pragma unroll
        for (int rh = 0; rh < 2; rh++) {
            int gm = bm0 + wm + mt * 16 + rh * 8 + lg;
            if (gm >= M) continue;
            #pragma unroll
            for (int nt = 0; nt < 4; nt++) {
                #pragma unroll
                for (int l = 0; l < 2; l++) {
                    int gn = bn0 + wn + nt * 8 + 2 * lq + l;
                    if (gn >= Nn) continue;
                    float v = acc[mt][nt][rh * 2 + l];
                    if (gn < S) {
                        if (biasQ) v += biasQ[gn];
                        if (do_relu) v = fmaxf(v, 0.f);
                        if (do_round) v = tf32r(v);
                        Cq[(size_t)gm * S + gn] = v;
                    } else {
                        if (biasA) v += biasA[gn - S];
                        Ca[(size_t)gm * Wa + (gn - S)] = v;
                    }
                }
            }
        }
    }
}

// ---------------- edge kernels (warp per edge; edge_index is int32) ----------------
__global__ void edge_l1(const float* __restrict__ ea, const int* __restrict__ ei, int E) {
    int e = blockIdx.x * (blockDim.x >> 5) + (threadIdx.x >> 5);
    if (e >= E) return;
    int lane = threadIdx.x & 31;
    float cv = (lane < E_DIM) ? ea[(size_t)e * E_DIM + lane] : (lane == E_DIM ? 1.f : 0.f);
    int src = ei[e];
    int dst = ei[E + e];
    if ((unsigned)src >= NN || (unsigned)dst >= NN) return;
    const float* q = g_q1 + (size_t)src * Q1W;
    float a0 = 0.f, a1 = 0.f;
    #pragma unroll
    for (int k = 0; k < KX; k++) {
        float ck = __shfl_sync(0xffffffffu, cv, k);
        a0 = fmaf(ck, q[k * H2 + lane], a0);
        a1 = fmaf(ck, q[k * H2 + lane + 32], a1);
    }
    atomicAdd(&g_agg1[(size_t)dst * H2 + lane], a0);
    atomicAdd(&g_agg1[(size_t)dst * H2 + lane + 32], a1);
}

__global__ void edge_l2(const float* __restrict__ ea, const int* __restrict__ ei, int E) {
    int e = blockIdx.x * (blockDim.x >> 5) + (threadIdx.x >> 5);
    if (e >= E) return;
    int lane = threadIdx.x & 31;
    float cv = (lane < E_DIM) ? ea[(size_t)e * E_DIM + lane] : (lane == E_DIM ? 1.f : 0.f);
    int src = ei[e];
    int dst = ei[E + e];
    if ((unsigned)src >= NN || (unsigned)dst >= NN) return;
    const float* q = g_q2 + (size_t)src * Q2W;
    float a = 0.f;
    #pragma unroll
    for (int k = 0; k < KX; k++) {
        float ck = __shfl_sync(0xffffffffu, cv, k);
        if (lane < CC) a = fmaf(ck, q[k * CC + lane], a);
    }
    if (lane < CC) atomicAdd(&g_agg2[(size_t)dst * CC + lane], a);
}

// ---------------- relu + log_softmax ----------------
__global__ void relu_copy(int n) {
    int i = blockIdx.x * blockDim.x + threadIdx.x;
    if (i < n) g_h2[i] = tf32r(fmaxf(g_agg1[i], 0.f));
}

__global__ void log_softmax_rows(float* __restrict__ out, int n) {
    int r = blockIdx.x * blockDim.x + threadIdx.x;
    if (r >= n) return;
    const float* z = g_agg2 + (size_t)r * CC;
    float m = z[0];
    #pragma unroll
    for (int c = 1; c < CC; c++) m = fmaxf(m, z[c]);
    float s = 0.f;
    #pragma unroll
    for (int c = 0; c < CC; c++) s += __expf(z[c] - m);
    float ls = m + logf(s);
    #pragma unroll
    for (int c = 0; c < CC; c++) out[(size_t)r * CC + c] = z[c] - ls;
}

// ---------------- launch ----------------
extern "C" void kernel_launch(void* const* d_in, const int* in_sizes, int n_in,
                              void* d_out, int out_size)
{
    const float* x     = (const float*)d_in[0];
    const float* ea    = (const float*)d_in[1];
    const int*   ei    = (const int*)d_in[2];
    const float* W1    = (const float*)d_in[3];
    const float* b1    = (const float*)d_in[4];
    const float* We1   = (const float*)d_in[5];
    const float* be1   = (const float*)d_in[6];
    const float* root1 = (const float*)d_in[7];
    const float* bias1 = (const float*)d_in[8];
    const float* We2   = (const float*)d_in[9];
    const float* be2   = (const float*)d_in[10];
    const float* root2 = (const float*)d_in[11];
    const float* bias2 = (const float*)d_in[12];
    float* out = (float*)d_out;

    int N = in_sizes[0] / D_IN;
    int E = in_sizes[2] / 2;

    float *p_h1, *p_q1, *p_agg1, *p_h2, *p_q2, *p_M1, *p_M2, *p_agg2, *p_xr, *p_W1r;
    cudaGetSymbolAddress((void**)&p_h1,   g_h1);
    cudaGetSymbolAddress((void**)&p_q1,   g_q1);
    cudaGetSymbolAddress((void**)&p_agg1, g_agg1);
    cudaGetSymbolAddress((void**)&p_h2,   g_h2);
    cudaGetSymbolAddress((void**)&p_q2,   g_q2);
    cudaGetSymbolAddress((void**)&p_M1,   g_M1);
    cudaGetSymbolAddress((void**)&p_M2,   g_M2);
    cudaGetSymbolAddress((void**)&p_agg2, g_agg2);
    cudaGetSymbolAddress((void**)&p_xr,   g_xr);
    cudaGetSymbolAddress((void**)&p_W1r,  g_W1r);

    static bool attr_set = false;
    if (!attr_set) {
        cudaFuncSetAttribute(tgemm, cudaFuncAttributeMaxDynamicSharedMemorySize, SMEM_BYTES);
        attr_set = true;
    }

    dim3 blk(256);

    // one merged prep launch: pack M1/M2 (tf32), round x and W1
    prep<<<(T_W1 + 255) / 256, blk>>>(We1, be1, root1, We2, be2, root2, x, W1);

    // h1 = round(relu(x @ W1 + b1))     [N,64]@[64,128]
    {
        dim3 g((H1 + GN - 1) / GN, (N + GM - 1) / GM);
        tgemm<<<g, blk, SMEM_BYTES>>>(p_xr, p_W1r, p_h1, p_h1, N, H1, D_IN, H1, b1, nullptr, 1, 1);
    }
    // fused q1|agg1 = h1 @ [M1|root1]   [N,128]@[128,1152]; split at 1088
    {
        dim3 g((B1W + GN - 1) / GN, (N + GM - 1) / GM);
        tgemm<<<g, blk, SMEM_BYTES>>>(p_h1, p_M1, p_q1, p_agg1, N, B1W, H1, Q1W, nullptr, bias1, 0, 0);
    }
    edge_l1<<<(E + 3) / 4, 128>>>(ea, ei, E);
    relu_copy<<<(N * H2 + 255) / 256, blk>>>(N * H2);
    // fused q2|agg2 = h2 @ [M2|root2]   [N,64]@[64,180]; split at 170
    {
        dim3 g((B2W + GN - 1) / GN, (N + GM - 1) / GM);
        tgemm<<<g, blk, SMEM_BYTES>>>(p_h2, p_M2, p_q2, p_agg2, N, B2W, H2, Q2W, nullptr, bias2, 0, 0);
    }
    edge_l2<<<(E + 3) / 4, 128>>>(ea, ei, E);
    log_softmax_rows<<<(N + 255) / 256, blk>>>(out, N);
}